// round 7
// baseline (speedup 1.0000x reference)
#include <cuda_runtime.h>
#include <math.h>

#define BATCH 32
#define MAXPV 50
#define RULENUM 256
#define ED 128
#define NPV (BATCH*MAXPV)   // 1600
#define LDA 132              // padded row stride for h3 in shared

// ---------------- scratch (device globals; no allocations allowed) ----------
__device__ float g_pemb[NPV*ED];
__device__ float g_vemb[NPV*ED];
__device__ float g_remb[RULENUM*ED];
__device__ float g_propemb[RULENUM*ED];
__device__ float g_pa[NPV*ED];
__device__ float g_pb[NPV*ED];
__device__ float g_pc[NPV*ED];
__device__ float g_ra[RULENUM*ED];
__device__ float g_rb[RULENUM*ED];
__device__ float g_rc[RULENUM*ED];
__device__ float g_propa[RULENUM*ED];
__device__ float g_rulemask[RULENUM];
__device__ float g_regpart[RULENUM];
__device__ float g_scores[BATCH*RULENUM];

__device__ __forceinline__ void split_tf32(float x, unsigned &hi, unsigned &lo){
    asm("cvt.rna.tf32.f32 %0, %1;" : "=r"(hi) : "f"(x));
    float h = __uint_as_float(hi);
    float l = x - h;
    asm("cvt.rna.tf32.f32 %0, %1;" : "=r"(lo) : "f"(l));
}

__device__ __forceinline__ void mma_tf32(float* c,
    unsigned a0, unsigned a1, unsigned a2, unsigned a3,
    unsigned b0, unsigned b1)
{
    asm volatile(
        "mma.sync.aligned.m16n8k8.row.col.f32.tf32.tf32.f32 "
        "{%0,%1,%2,%3}, {%4,%5,%6,%7}, {%8,%9}, {%0,%1,%2,%3};"
        : "+f"(c[0]), "+f"(c[1]), "+f"(c[2]), "+f"(c[3])
        : "r"(a0), "r"(a1), "r"(a2), "r"(a3), "r"(b0), "r"(b1));
}

// ---------------- kernel 1: gather + l2 normalize ---------------------------
__global__ void norm_gather_kernel(const int* __restrict__ prop,
                                   const int* __restrict__ val,
                                   const float* __restrict__ ent,
                                   const float* __restrict__ rule)
{
    int row = blockIdx.x;
    int k = threadIdx.x;
    const float* src; float* dst;
    if (row < NPV)            { src = ent + (size_t)prop[row]*ED;              dst = g_pemb + row*ED; }
    else if (row < 2*NPV)     { int t=row-NPV;   src = ent + (size_t)val[t]*ED; dst = g_vemb + t*ED; }
    else if (row < 2*NPV+256) { int t=row-2*NPV; src = rule + t*ED;            dst = g_remb + t*ED; }
    else                      { int t=row-2*NPV-256; src = ent + (size_t)t*ED; dst = g_propemb + t*ED; }

    float x = src[k];
    float s = x*x;
    #pragma unroll
    for (int o=16;o>0;o>>=1) s += __shfl_xor_sync(0xffffffffu, s, o);
    __shared__ float ws[4];
    if ((k&31)==0) ws[k>>5] = s;
    __syncthreads();
    float tot = ws[0]+ws[1]+ws[2]+ws[3];
    float n = fmaxf(sqrtf(tot), 1e-12f);
    dst[k] = x / n;
}

// ---------------- kernel 2: all small 128x128 GEMMs -------------------------
__global__ void small_gemm_kernel(const float* __restrict__ fc1w, const float* __restrict__ fc1b,
                                  const float* __restrict__ fc2w, const float* __restrict__ fc2b,
                                  const float* __restrict__ fc3w, const float* __restrict__ fc3b)
{
    int row = blockIdx.x, k = threadIdx.x;
    const float *in, *W; const float* bias = nullptr; float* out;
    if (row < 1600)      { in=g_pemb+row*ED;            W=fc1w;        out=g_pa+row*ED; }
    else if (row < 3200) { int t=row-1600; in=g_pemb+t*ED; W=fc2w;     out=g_pb+t*ED; }
    else if (row < 4800) { int t=row-3200; in=g_pemb+t*ED; W=fc3w;     out=g_pc+t*ED; }
    else if (row < 5056) { int t=row-4800; in=g_remb+t*ED; W=fc1w+ED*ED; bias=fc1b; out=g_ra+t*ED; }
    else if (row < 5312) { int t=row-5056; in=g_remb+t*ED; W=fc2w+ED*ED; bias=fc2b; out=g_rb+t*ED; }
    else if (row < 5568) { int t=row-5312; in=g_remb+t*ED; W=fc3w+ED*ED; bias=fc3b; out=g_rc+t*ED; }
    else                 { int t=row-5568; in=g_propemb+t*ED; W=fc1w;  out=g_propa+t*ED; }

    __shared__ float inrow[ED];
    inrow[k] = in[k];
    __syncthreads();
    float acc = bias ? bias[k] : 0.f;
    #pragma unroll 8
    for (int i=0;i<ED;i++) acc = fmaf(inrow[i], __ldg(W + i*ED + k), acc);
    out[k] = acc;
}

// ---------------- kernel 3: pi matrix -> rule_mask + reg partials -----------
__global__ void pi_kernel(const float* __restrict__ fc4w, const float* __restrict__ fc4b)
{
    int r = blockIdx.x;
    int tid = threadIdx.x, lane = tid&31, w = tid>>5;
    __shared__ float rarow[ED], f4s[ED];
    if (tid < ED){ rarow[tid] = g_ra[r*ED+tid]; f4s[tid] = fc4w[tid]; }
    __syncthreads();
    float fb4 = fc4b[0];
    float mask_s = 0.f, reg_s = 0.f;
    for (int pp=0; pp<32; pp++){
        int p = w*32 + pp;
        float s = 0.f;
        #pragma unroll
        for (int q=0;q<4;q++){
            int i = lane*4 + q;
            float h = fmaxf(g_propa[p*ED + i] + rarow[i], 0.f);
            s = fmaf(h, f4s[i], s);
        }
        #pragma unroll
        for (int o=16;o>0;o>>=1) s += __shfl_xor_sync(0xffffffffu, s, o);
        if (lane==0){
            float piv = 1.f/(1.f+expf(-(s+fb4)));
            if (piv > 0.5f) mask_s += piv;
            float diag = (r==p) ? 1.f : 0.f;
            float rv = piv*diag + (1.f-piv)*(1.f-diag);
            reg_s += -logf(rv + 1e-8f) * ((1.f-diag) + diag*(float)RULENUM);
        }
    }
    __shared__ float ms[8], rs[8];
    if (lane==0){ ms[w]=mask_s; rs[w]=reg_s; }
    __syncthreads();
    if (tid==0){
        float m=0.f, rg=0.f;
        #pragma unroll
        for (int i=0;i<8;i++){ m+=ms[i]; rg+=rs[i]; }
        g_rulemask[r] = m + 1.f;
        g_regpart[r]  = rg;
    }
}

// ---------------- kernel 4: main (b,r) scoring, tensor-core GEMM -------------
// One 256-thread block per (r,b).
// Phase A: compute h3 rows (50, padded to 64) into shared; h1/h2 score
//          partials via truncated butterfly -> sp.
// Phase B: y = h3 @ fc6 as m16n8k8 tf32 mma, 3xtf32 split (fp32 accuracy).
//          Each of 8 warps owns 16 output cols; fc6 hi/lo frags in registers.
// Phase C: per-row y^2 / y.v reduction -> scores.
__global__ void __launch_bounds__(256, 1) main_kernel(
    const int* __restrict__ samemask, const int* __restrict__ padmask,
    const float* __restrict__ fc4w, const float* __restrict__ fc4b,
    const float* __restrict__ fc5w, const float* __restrict__ fc5b,
    const float* __restrict__ fc6w, const float* __restrict__ fc6b)
{
    int r = blockIdx.x, b = blockIdx.y;
    int t = threadIdx.x, lane = t&31, w = t>>5;
    int gid = lane>>2, tig = lane&3;   // groupID, threadID-in-group

    __shared__ __align__(16) float h3s[64*LDA];
    __shared__ float2 sp[MAXPV][16];
    __shared__ float2 yred[64][8];
    __shared__ float scj[64];

    // ---- B (fc6) fragment preload: warp w owns cols [w*16, w*16+16) ----
    int cb = w*16;
    unsigned bh[2][16][2], bl[2][16][2];
    #pragma unroll
    for (int nt=0; nt<2; nt++){
        int col = cb + nt*8 + gid;
        #pragma unroll
        for (int kt=0; kt<16; kt++){
            int k0 = kt*8 + tig;
            split_tf32(fc6w[k0*ED + col],     bh[nt][kt][0], bl[nt][kt][0]);
            split_tf32(fc6w[(k0+4)*ED + col], bh[nt][kt][1], bl[nt][kt][1]);
        }
    }

    // ---- zero pad rows 50..63 (incl padding cols) ----
    for (int i=t; i < 14*LDA; i += 256) h3s[50*LDA + i] = 0.f;

    // ---- Phase A: h3 + h1/h2 partial dots ----
    {
        int k = t & 127, jsel = t >> 7;
        float ra_k = g_ra[r*ED+k], rb_k = g_rb[r*ED+k], rc_k = g_rc[r*ED+k];
        float f4 = fc4w[k], f5 = fc5w[k];
        for (int j=jsel; j<MAXPV; j+=2){
            int base = (b*MAXPV + j)*ED + k;
            float h1 = fmaxf(g_pa[base] + ra_k, 0.f);
            float h2 = fmaxf(g_pb[base] + rb_k, 0.f);
            h3s[j*LDA + k] = fmaxf(g_pc[base] + rc_k, 0.f);
            float u = h1*f4, q = h2*f5;
            #pragma unroll
            for (int o=16;o>=4;o>>=1){
                u += __shfl_xor_sync(0xffffffffu, u, o);
                q += __shfl_xor_sync(0xffffffffu, q, o);
            }
            if (lane < 4) sp[j][(w&3)*4 + lane] = make_float2(u, q);
        }
    }
    __syncthreads();

    // ---- Phase B: mma over K=128 (16 k-tiles), M=64 (4 m-tiles), N=16 (2 n-tiles)
    float C[4][2][4];
    #pragma unroll
    for (int mt=0;mt<4;mt++)
        #pragma unroll
        for (int nt=0;nt<2;nt++)
            #pragma unroll
            for (int q=0;q<4;q++) C[mt][nt][q] = 0.f;

    #pragma unroll
    for (int kt=0; kt<16; kt++){
        unsigned ah[4][4], al[4][4];
        int kc = kt*8 + tig;
        #pragma unroll
        for (int mt=0; mt<4; mt++){
            int row = mt*16 + gid;
            split_tf32(h3s[ row   *LDA + kc  ], ah[mt][0], al[mt][0]);
            split_tf32(h3s[(row+8)*LDA + kc  ], ah[mt][1], al[mt][1]);
            split_tf32(h3s[ row   *LDA + kc+4], ah[mt][2], al[mt][2]);
            split_tf32(h3s[(row+8)*LDA + kc+4], ah[mt][3], al[mt][3]);
        }
        #pragma unroll
        for (int mt=0; mt<4; mt++){
            #pragma unroll
            for (int nt=0; nt<2; nt++){
                mma_tf32(C[mt][nt], ah[mt][0],ah[mt][1],ah[mt][2],ah[mt][3],
                         bh[nt][kt][0], bh[nt][kt][1]);
                mma_tf32(C[mt][nt], ah[mt][0],ah[mt][1],ah[mt][2],ah[mt][3],
                         bl[nt][kt][0], bl[nt][kt][1]);
                mma_tf32(C[mt][nt], al[mt][0],al[mt][1],al[mt][2],al[mt][3],
                         bh[nt][kt][0], bh[nt][kt][1]);
            }
        }
    }

    // ---- Phase C: per-row y^2 and y.v partials ----
    {
        // cols for this thread: per nt: col0 = cb + nt*8 + tig*2, col1 = col0+1
        float b60 = fc6b[cb + tig*2],      b61 = fc6b[cb + tig*2 + 1];
        float b62 = fc6b[cb + 8 + tig*2],  b63 = fc6b[cb + 8 + tig*2 + 1];
        #pragma unroll
        for (int mt=0; mt<4; mt++){
            int rowA = mt*16 + gid;
            int rowB = rowA + 8;
            float yyA=0.f, yvA=0.f, yyB=0.f, yvB=0.f;
            #pragma unroll
            for (int nt=0; nt<2; nt++){
                int col0 = cb + nt*8 + tig*2;
                float bb0 = nt ? b62 : b60;
                float bb1 = nt ? b63 : b61;
                float y0 = C[mt][nt][0] + bb0;
                float y1 = C[mt][nt][1] + bb1;
                float y2 = C[mt][nt][2] + bb0;
                float y3 = C[mt][nt][3] + bb1;
                float v0=0.f, v1=0.f, v2=0.f, v3=0.f;
                if (rowA < MAXPV){
                    v0 = g_vemb[(b*MAXPV+rowA)*ED + col0];
                    v1 = g_vemb[(b*MAXPV+rowA)*ED + col0 + 1];
                }
                if (rowB < MAXPV){
                    v2 = g_vemb[(b*MAXPV+rowB)*ED + col0];
                    v3 = g_vemb[(b*MAXPV+rowB)*ED + col0 + 1];
                }
                yyA += y0*y0 + y1*y1;  yvA += y0*v0 + y1*v1;
                yyB += y2*y2 + y3*y3;  yvB += y2*v2 + y3*v3;
            }
            // reduce over the 4 lanes sharing these rows (tig = 0..3)
            #pragma unroll
            for (int o=1;o<=2;o<<=1){
                yyA += __shfl_xor_sync(0xffffffffu, yyA, o);
                yvA += __shfl_xor_sync(0xffffffffu, yvA, o);
                yyB += __shfl_xor_sync(0xffffffffu, yyB, o);
                yvB += __shfl_xor_sync(0xffffffffu, yvB, o);
            }
            if (tig == 0){
                yred[rowA][w] = make_float2(yyA, yvA);
                yred[rowB][w] = make_float2(yyB, yvB);
            }
        }
    }
    __syncthreads();

    // ---- scoring ----
    float fb4 = fc4b[0], fb5 = fc5b[0];
    if (t < MAXPV){
        float s1d=0.f, pd=0.f;
        #pragma unroll
        for (int i=0;i<16;i++){
            float2 q = sp[t][i];
            s1d += q.x; pd += q.y;
        }
        float yn2=0.f, ydv=0.f;
        #pragma unroll
        for (int i=0;i<8;i++){
            float2 q = yred[t][i];
            yn2 += q.x; ydv += q.y;
        }
        float s1 = 1.f/(1.f+expf(-(s1d+fb4)));
        float p  = 1.f/(1.f+expf(-(pd +fb5)));
        float yn = sqrtf(yn2);
        float cosv = ydv / fmaxf(yn, 1e-8f);   // v_emb unit-norm; gv = y/||y||
        float s2 = 0.5f*cosv + 0.5f;
        float sc = p + (1.f-p)*s2;
        sc = (samemask[b*MAXPV+t]==1) ? (s1*sc) : (1.f - s1);
        sc *= (float)padmask[b*MAXPV+t];
        if (!(s1 > 0.5f)) sc = 0.f;
        scj[t] = sc;
    }
    __syncthreads();
    if (t < 32){
        float s = scj[t];
        if (t + 32 < MAXPV) s += scj[t+32];
        #pragma unroll
        for (int o=16;o>0;o>>=1) s += __shfl_xor_sync(0xffffffffu, s, o);
        if (t==0) g_scores[b*RULENUM + r] = s / g_rulemask[r];
    }
}

// ---------------- kernel 5: deterministic finalize ---------------------------
__global__ void finalize_kernel(float* __restrict__ out, int out_size)
{
    int tid = threadIdx.x, lane = tid&31, w = tid>>5;  // 256 threads, 8 warps
    float rg = g_regpart[tid];
    #pragma unroll
    for (int o=16;o>0;o>>=1) rg += __shfl_xor_sync(0xffffffffu, rg, o);
    __shared__ float rs[8];
    if (lane==0) rs[w] = rg;
    __syncthreads();
    if (tid==0 && out_size > BATCH){
        float t=0.f;
        #pragma unroll
        for (int i=0;i<8;i++) t += rs[i];
        out[BATCH] = t / (float)(RULENUM*RULENUM);
    }
    #pragma unroll
    for (int q=0;q<4;q++){
        int b = w*4 + q;
        float m = -1e30f;
        for (int c=lane;c<RULENUM;c+=32) m = fmaxf(m, g_scores[b*RULENUM+c]);
        #pragma unroll
        for (int o=16;o>0;o>>=1) m = fmaxf(m, __shfl_xor_sync(0xffffffffu, m, o));
        if (lane==0 && b < out_size) out[b] = m;
    }
}

// ---------------- launch -----------------------------------------------------
extern "C" void kernel_launch(void* const* d_in, const int* in_sizes, int n_in,
                              void* d_out, int out_size)
{
    const int*   prop = (const int*)d_in[0];
    const int*   val  = (const int*)d_in[1];
    const int*   same = (const int*)d_in[2];
    const int*   pad  = (const int*)d_in[3];
    const float* rule = (const float*)d_in[4];
    const float* ent  = (const float*)d_in[5];
    const float* fc1w = (const float*)d_in[6];
    const float* fc1b = (const float*)d_in[7];
    const float* fc2w = (const float*)d_in[8];
    const float* fc2b = (const float*)d_in[9];
    const float* fc3w = (const float*)d_in[10];
    const float* fc3b = (const float*)d_in[11];
    const float* fc4w = (const float*)d_in[12];
    const float* fc4b = (const float*)d_in[13];
    const float* fc5w = (const float*)d_in[14];
    const float* fc5b = (const float*)d_in[15];
    const float* fc6w = (const float*)d_in[16];
    const float* fc6b = (const float*)d_in[17];

    norm_gather_kernel<<<2*NPV + 2*RULENUM, 128>>>(prop, val, ent, rule);
    small_gemm_kernel<<<3*NPV + 4*RULENUM, 128>>>(fc1w, fc1b, fc2w, fc2b, fc3w, fc3b);
    pi_kernel<<<RULENUM, 256>>>(fc4w, fc4b);
    main_kernel<<<dim3(RULENUM, BATCH), 256>>>(same, pad, fc4w, fc4b, fc5w, fc5b, fc6w, fc6b);
    finalize_kernel<<<1, 256>>>((float*)d_out, out_size);
}